// round 1
// baseline (speedup 1.0000x reference)
#include <cuda_runtime.h>
#include <math.h>

#define T_STEPS 4096
#define VOCAB   1024
#define STATE   2048
#define CDIM    3072
#define NBLK    148
#define NTHR    512
#define NWARP   16

// Persistent cross-step state (device globals: allocation-free scratch).
__device__ float    g_h1[CDIM];
__device__ float    g_h2[CDIM];
__device__ float    g_state[STATE];
__device__ unsigned g_count;   // zero-init; self-resets every barrier
__device__ unsigned g_flag;    // zero-init; sense parity returns to 0 (12288 barriers, even)

// Software grid barrier, sense-reversal. All CTAs resident (grid == #SMs, occupancy 1).
__device__ __forceinline__ void grid_sync(unsigned sense) {
    __threadfence();           // make this thread's global stores visible chip-wide
    __syncthreads();
    if (threadIdx.x == 0) {
        unsigned a = atomicAdd(&g_count, 1u) + 1u;
        if (a == (unsigned)gridDim.x) {
            atomicExch(&g_count, 0u);   // reset BEFORE release
            __threadfence();
            atomicExch(&g_flag, sense); // release
        } else {
            unsigned f;
            do {
                asm volatile("ld.volatile.global.u32 %0, [%1];"
                             : "=r"(f) : "l"(&g_flag));
            } while (f != sense);
        }
    }
    __syncthreads();
}

// Dot of one 3072-wide weight row against the shared input vector. Warp-collective.
__device__ __forceinline__ float row_dot(const float4* __restrict__ w4,
                                         const float4* __restrict__ sv4,
                                         int lane) {
    float4 acc = make_float4(0.f, 0.f, 0.f, 0.f);
#pragma unroll
    for (int i = 0; i < CDIM / 128; i++) {       // 24 iterations, 16B/lane each
        float4 w = __ldg(&w4[lane + 32 * i]);
        float4 v = sv4[lane + 32 * i];
        acc.x = fmaf(w.x, v.x, acc.x);
        acc.y = fmaf(w.y, v.y, acc.y);
        acc.z = fmaf(w.z, v.z, acc.z);
        acc.w = fmaf(w.w, v.w, acc.w);
    }
    float s = (acc.x + acc.y) + (acc.z + acc.w);
#pragma unroll
    for (int o = 16; o; o >>= 1)
        s += __shfl_xor_sync(0xffffffffu, s, o);
    return s;
}

__global__ void __launch_bounds__(NTHR, 1)
rnn_kernel(const float* __restrict__ x,     const float* __restrict__ state0,
           const float* __restrict__ W1,    const float* __restrict__ B1,
           const float* __restrict__ W2,    const float* __restrict__ B2,
           const float* __restrict__ W3,    const float* __restrict__ B3,
           float* __restrict__ out) {
    __shared__ float sv[CDIM];
    const int tid  = threadIdx.x;
    const int lane = tid & 31;
    const int warp = tid >> 5;
    const int b    = blockIdx.x;

    // Static row partition: CTAs 0..111 get 21 rows, 112..147 get 20 (sum = 3072).
    const int extra  = (b < 112) ? b : 112;
    const int rstart = b * 20 + extra;
    const int rcount = 20 + (b < 112 ? 1 : 0);

    const float4* sv4 = (const float4*)sv;
    unsigned sense = 0;

    for (int t = 0; t < T_STEPS; t++) {
        // ---- Stage input vector: [x_t (1024) | state (2048)] into shared ----
        for (int i = tid; i < VOCAB; i += NTHR)
            sv[i] = __ldg(&x[(size_t)t * VOCAB + i]);
        if (t == 0) {
            for (int i = tid; i < STATE; i += NTHR)
                sv[VOCAB + i] = __ldg(&state0[i]);
        } else {
            for (int i = tid; i < STATE; i += NTHR)
                sv[VOCAB + i] = __ldcg(&g_state[i]);   // written by other CTAs: bypass L1
        }
        __syncthreads();

        // ---- Layer 1: h1 = tanh(W1 @ v + B1) ----
        for (int r = warp; r < rcount; r += NWARP) {
            int j = rstart + r;
            float s = row_dot((const float4*)(W1 + (size_t)j * CDIM), sv4, lane);
            if (lane == 0) g_h1[j] = tanhf(s + __ldg(&B1[j]));
        }
        sense ^= 1; grid_sync(sense);

        for (int i = tid; i < CDIM; i += NTHR) sv[i] = __ldcg(&g_h1[i]);
        __syncthreads();

        // ---- Layer 2: h2 = tanh(W2 @ h1 + B2) ----
        for (int r = warp; r < rcount; r += NWARP) {
            int j = rstart + r;
            float s = row_dot((const float4*)(W2 + (size_t)j * CDIM), sv4, lane);
            if (lane == 0) g_h2[j] = tanhf(s + __ldg(&B2[j]));
        }
        sense ^= 1; grid_sync(sense);

        for (int i = tid; i < CDIM; i += NTHR) sv[i] = __ldcg(&g_h2[i]);
        __syncthreads();

        // ---- Layer 3: o = W3 @ h2 + B3 ; logits -> out, tail -> state ----
        for (int r = warp; r < rcount; r += NWARP) {
            int j = rstart + r;
            float s = row_dot((const float4*)(W3 + (size_t)j * CDIM), sv4, lane);
            if (lane == 0) {
                float o = s + __ldg(&B3[j]);
                if (j < VOCAB) {
                    out[(size_t)t * VOCAB + j] = o;
                } else {
                    g_state[j - VOCAB] = o;
                    if (t == T_STEPS - 1)
                        out[(size_t)T_STEPS * VOCAB + (j - VOCAB)] = o;  // s_final
                }
            }
        }
        sense ^= 1; grid_sync(sense);
    }
}

extern "C" void kernel_launch(void* const* d_in, const int* in_sizes, int n_in,
                              void* d_out, int out_size) {
    const float* x  = (const float*)d_in[0];
    const float* st = (const float*)d_in[1];
    const float* W1 = (const float*)d_in[2];
    const float* B1 = (const float*)d_in[3];
    const float* W2 = (const float*)d_in[4];
    const float* B2 = (const float*)d_in[5];
    const float* W3 = (const float*)d_in[6];
    const float* B3 = (const float*)d_in[7];
    (void)in_sizes; (void)n_in; (void)out_size;
    rnn_kernel<<<NBLK, NTHR>>>(x, st, W1, B1, W2, B2, W3, B3, (float*)d_out);
}

// round 2
// speedup vs baseline: 2.0177x; 2.0177x over previous
#include <cuda_runtime.h>
#include <cuda_fp16.h>
#include <math.h>

#define T_STEPS 4096
#define VOCAB   1024
#define STATE   2048
#define CDIM    3072
#define NEL     (CDIM*CDIM)
#define NBLK    148
#define NTHR    1024
#define PIN_L2  12                      // pinned layer-2 local rows (multiple of 4)
#define MAXPIN  33                      // max pinned rows per CTA (<= 21 + 12)
#define PIN_BYTES (MAXPIN*CDIM*2)       // 202752 B of fp16 weights in smem
#define SV_OFF    PIN_BYTES
#define SPRE_OFF  (SV_OFF + CDIM*4)     // sv: 12288 B
#define SMEM_TOTAL (SPRE_OFF + 4*32*4)  // spre: 512 B  -> 215552 total

// ---- persistent device state (allocation-free scratch) ----
__device__ __half   g_wh[3*(size_t)NEL];   // fp16 weights: W1 | W2 | W3 (row-major)
__device__ float    g_h1[CDIM];
__device__ float    g_h2[CDIM];
__device__ float    g_state[STATE];
__device__ unsigned g_count;               // self-resets
__device__ unsigned g_flag;                // ends at 0 (12288 barriers, even)

// ---- software grid barrier (sense reversal) ----
__device__ __forceinline__ void grid_sync(unsigned sense) {
    __threadfence();
    __syncthreads();
    if (threadIdx.x == 0) {
        unsigned a = atomicAdd(&g_count, 1u) + 1u;
        if (a == (unsigned)gridDim.x) {
            atomicExch(&g_count, 0u);
            __threadfence();
            atomicExch(&g_flag, sense);
        } else {
            unsigned f;
            do {
                asm volatile("ld.volatile.global.u32 %0, [%1];" : "=r"(f) : "l"(&g_flag));
            } while (f != sense);
            __threadfence();   // acquire: order subsequent global reads after flag
        }
    }
    __syncthreads();
}

// ---- fp32->fp16 weight conversion (runs once per launch, ~60us) ----
__global__ void conv_kernel(const float* __restrict__ W1,
                            const float* __restrict__ W2,
                            const float* __restrict__ W3) {
    size_t i = (size_t)blockIdx.x * blockDim.x + threadIdx.x;
    size_t stride = (size_t)gridDim.x * blockDim.x;
    const float2* w1 = (const float2*)W1;
    const float2* w2 = (const float2*)W2;
    const float2* w3 = (const float2*)W3;
    __half2* o1 = (__half2*)g_wh;
    __half2* o2 = (__half2*)(g_wh + NEL);
    __half2* o3 = (__half2*)(g_wh + 2*(size_t)NEL);
    for (; i < NEL/2; i += stride) {
        float2 a = w1[i]; o1[i] = __floats2half2_rn(a.x, a.y);
        float2 b = w2[i]; o2[i] = __floats2half2_rn(b.x, b.y);
        float2 c = w3[i]; o3[i] = __floats2half2_rn(c.x, c.y);
    }
}

// ---- 4-row x K/4 partial GEMV; v loaded once per 4 rows ----
template<bool PIN>
__device__ __forceinline__ void quad_accum(
    const __half* w0, const __half* w1, const __half* w2, const __half* w3,
    const float* __restrict__ sv, int kbase, int lane, float acc[4])
{
#pragma unroll
    for (int i = 0; i < 6; i++) {
        int k = kbase + (i*32 + lane)*4;
        float4 v = *(const float4*)(sv + k);
#define ROW(AC, WP) do {                                                     \
        uint2 wa = PIN ? *(const uint2*)((WP) + k)                           \
                       : __ldg((const uint2*)((WP) + k));                    \
        float2 fa = __half22float2(*(const __half2*)&wa.x);                  \
        float2 fb = __half22float2(*(const __half2*)&wa.y);                  \
        AC = fmaf(fa.x, v.x, AC); AC = fmaf(fa.y, v.y, AC);                  \
        AC = fmaf(fb.x, v.z, AC); AC = fmaf(fb.y, v.w, AC); } while (0)
        ROW(acc[0], w0);
        ROW(acc[1], w1);
        ROW(acc[2], w2);
        ROW(acc[3], w3);
#undef ROW
    }
}

// ---- one layer: rows [rstart, rstart+rcount) against sv, partials -> spre ----
__device__ __forceinline__ void run_layer(
    const __half* __restrict__ gw,   // global base of this layer's weights
    const __half* wpin,              // smem base of this layer's pinned rows
    int pin_rows,                    // leading local rows pinned in smem
    int rstart, int rcount,
    const float* __restrict__ sv, float* __restrict__ spre,
    int warp, int lane)
{
    int nquads = (rcount + 3) >> 2;
    if (warp >= nquads*4) return;
    int quad = warp >> 2;
    int ks   = warp & 3;
    int r0   = quad * 4;
    int kbase = ks * (CDIM/4);

    int l0 = r0;
    int l1 = (r0+1 < rcount) ? r0+1 : rcount-1;
    int l2 = (r0+2 < rcount) ? r0+2 : rcount-1;
    int l3 = (r0+3 < rcount) ? r0+3 : rcount-1;

    float acc[4] = {0.f, 0.f, 0.f, 0.f};
    if (r0 < pin_rows) {   // pin boundary never straddles a quad
        quad_accum<true>(wpin + l0*CDIM, wpin + l1*CDIM,
                         wpin + l2*CDIM, wpin + l3*CDIM, sv, kbase, lane, acc);
    } else {
        quad_accum<false>(gw + (size_t)(rstart+l0)*CDIM, gw + (size_t)(rstart+l1)*CDIM,
                          gw + (size_t)(rstart+l2)*CDIM, gw + (size_t)(rstart+l3)*CDIM,
                          sv, kbase, lane, acc);
    }
#pragma unroll
    for (int r = 0; r < 4; r++) {
#pragma unroll
        for (int o = 16; o; o >>= 1)
            acc[r] += __shfl_xor_sync(0xffffffffu, acc[r], o);
        if (lane == 0 && (r0 + r) < rcount)
            spre[ks*32 + r0 + r] = acc[r];   // deterministic per-slot write
    }
}

__global__ void __launch_bounds__(NTHR, 1)
rnn_kernel(const float* __restrict__ x,  const float* __restrict__ state0,
           const float* __restrict__ B1, const float* __restrict__ B2,
           const float* __restrict__ B3, float* __restrict__ out) {
    extern __shared__ char smem[];
    __half* wpin = (__half*)smem;
    float*  sv   = (float*)(smem + SV_OFF);
    float*  spre = (float*)(smem + SPRE_OFF);

    const int tid  = threadIdx.x;
    const int lane = tid & 31;
    const int warp = tid >> 5;
    const int b    = blockIdx.x;

    // rows per CTA: 21 for b<112, else 20 (sum = 3072)
    const int rcount = 20 + (b < 112 ? 1 : 0);
    const int rstart = b*20 + (b < 112 ? b : 112);
    const int npin   = rcount + PIN_L2;   // L1 fully pinned + 12 rows of L2

    // ---- stage pinned weight rows into smem (once per launch) ----
    {
        int nvec = npin * (CDIM/8);       // uint4 = 8 halfs
        for (int idx = tid; idx < nvec; idx += NTHR) {
            int p = idx / (CDIM/8);
            int c = idx % (CDIM/8);
            int l, local;
            if (p < rcount) { l = 0; local = p; }
            else            { l = 1; local = p - rcount; }
            const uint4* src = (const uint4*)(g_wh + (size_t)l*NEL + (size_t)(rstart+local)*CDIM);
            ((uint4*)(wpin + p*CDIM))[c] = src[c];
        }
    }
    __syncthreads();

    unsigned sense = 0;
    for (int t = 0; t < T_STEPS; t++) {
        // ---------- layer 1 input: [x_t | state] ----------
        for (int i = tid; i < VOCAB; i += NTHR)
            sv[i] = __ldg(&x[(size_t)t * VOCAB + i]);
        if (t == 0) {
            for (int i = tid; i < STATE; i += NTHR) sv[VOCAB+i] = __ldg(&state0[i]);
        } else {
            for (int i = tid; i < STATE; i += NTHR) sv[VOCAB+i] = __ldcg(&g_state[i]);
        }
        if (tid < 128) spre[tid] = 0.f;
        __syncthreads();

        run_layer(g_wh, wpin, rcount, rstart, rcount, sv, spre, warp, lane);
        __syncthreads();
        if (tid < rcount) {
            int j = rstart + tid;
            float s = spre[tid] + spre[32+tid] + spre[64+tid] + spre[96+tid] + __ldg(&B1[j]);
            g_h1[j] = tanhf(s);
        }
        sense ^= 1; grid_sync(sense);

        // ---------- layer 2 ----------
        for (int i = tid; i < CDIM; i += NTHR) sv[i] = __ldcg(&g_h1[i]);
        if (tid < 128) spre[tid] = 0.f;
        __syncthreads();

        run_layer(g_wh + NEL, wpin + rcount*CDIM, PIN_L2, rstart, rcount, sv, spre, warp, lane);
        __syncthreads();
        if (tid < rcount) {
            int j = rstart + tid;
            float s = spre[tid] + spre[32+tid] + spre[64+tid] + spre[96+tid] + __ldg(&B2[j]);
            g_h2[j] = tanhf(s);
        }
        sense ^= 1; grid_sync(sense);

        // ---------- layer 3 ----------
        for (int i = tid; i < CDIM; i += NTHR) sv[i] = __ldcg(&g_h2[i]);
        if (tid < 128) spre[tid] = 0.f;
        __syncthreads();

        run_layer(g_wh + 2*(size_t)NEL, wpin, 0, rstart, rcount, sv, spre, warp, lane);
        __syncthreads();
        if (tid < rcount) {
            int j = rstart + tid;
            float o = spre[tid] + spre[32+tid] + spre[64+tid] + spre[96+tid] + __ldg(&B3[j]);
            if (j < VOCAB) {
                out[(size_t)t * VOCAB + j] = o;
            } else {
                g_state[j - VOCAB] = o;
                if (t == T_STEPS-1)
                    out[(size_t)T_STEPS * VOCAB + (j - VOCAB)] = o;
            }
        }
        sense ^= 1; grid_sync(sense);
    }
}

extern "C" void kernel_launch(void* const* d_in, const int* in_sizes, int n_in,
                              void* d_out, int out_size) {
    const float* x  = (const float*)d_in[0];
    const float* st = (const float*)d_in[1];
    const float* W1 = (const float*)d_in[2];
    const float* B1 = (const float*)d_in[3];
    const float* W2 = (const float*)d_in[4];
    const float* B2 = (const float*)d_in[5];
    const float* W3 = (const float*)d_in[6];
    const float* B3 = (const float*)d_in[7];
    (void)in_sizes; (void)n_in; (void)out_size;

    cudaFuncSetAttribute(rnn_kernel, cudaFuncAttributeMaxDynamicSharedMemorySize, SMEM_TOTAL);

    conv_kernel<<<2048, 256>>>(W1, W2, W3);
    rnn_kernel<<<NBLK, NTHR, SMEM_TOTAL>>>(x, st, B1, B2, B3, (float*)d_out);
}

// round 4
// speedup vs baseline: 2.8203x; 1.3978x over previous
#include <cuda_runtime.h>
#include <cuda_fp16.h>
#include <math.h>

#define T_STEPS 4096
#define VOCAB   1024
#define STATE   2048
#define CDIM    3072
#define NEL     (CDIM*CDIM)
#define NBLK    148
#define NTHR    1024
#define NCOMPW  28                 // compute warps (warps 0..27)
#define NCHUNK  3
#define CHUNK   1024
#define PIN_L2  12
#define MAXPIN  33
#define PIN_BYTES (MAXPIN*CDIM*2)
#define SV_OFF    PIN_BYTES
#define SPRE_OFF  (SV_OFF + CDIM*4)
#define SMEM_TOTAL (SPRE_OFF + 4*32*4)

#define CNT_FWD (NCOMPW*32 + 32)   // 928: 896 compute + 32 stager
#define CNT_CMP (NCOMPW*32)        // 896

#define BAR_SYNC(id,cnt)   asm volatile("bar.sync %0, %1;"   :: "r"(id), "r"(cnt) : "memory")
#define BAR_ARRIVE(id,cnt) asm volatile("bar.arrive %0, %1;" :: "r"(id), "r"(cnt) : "memory")

// ---- persistent device state ----
__device__ __half   g_wh[3*(size_t)NEL];
__device__ float    g_h1[2][CDIM];
__device__ float    g_h2[2][CDIM];
__device__ float    g_state[2][STATE];
__device__ unsigned g_cnt[3][NCHUNK];    // cumulative per (producer-layer, chunk)
__device__ unsigned g_scount, g_sflag;   // start barrier (replay-safe)

// ---- launch-start barrier: last arriver resets counters, then releases ----
__device__ __forceinline__ void start_barrier() {
    __syncthreads();
    if (threadIdx.x == 0) {
        unsigned F0;
        asm volatile("ld.volatile.global.u32 %0,[%1];" : "=r"(F0) : "l"(&g_sflag) : "memory");
        unsigned a = atomicAdd(&g_scount, 1u) + 1u;
        if (a == (unsigned)gridDim.x) {
            for (int l = 0; l < 3; l++)
                for (int k = 0; k < NCHUNK; k++) g_cnt[l][k] = 0u;
            atomicExch(&g_scount, 0u);
            __threadfence();
            atomicAdd(&g_sflag, 1u);
        } else {
            unsigned f;
            do {
                asm volatile("ld.volatile.global.u32 %0,[%1];" : "=r"(f) : "l"(&g_sflag) : "memory");
            } while (f == F0);
            __threadfence();
        }
    }
    __syncthreads();
}

// ---- fp32->fp16 conversion (idempotent, once per launch) ----
__global__ void conv_kernel(const float* __restrict__ W1,
                            const float* __restrict__ W2,
                            const float* __restrict__ W3) {
    size_t i = (size_t)blockIdx.x * blockDim.x + threadIdx.x;
    size_t stride = (size_t)gridDim.x * blockDim.x;
    const float2* w1 = (const float2*)W1;
    const float2* w2 = (const float2*)W2;
    const float2* w3 = (const float2*)W3;
    __half2* o1 = (__half2*)g_wh;
    __half2* o2 = (__half2*)(g_wh + (size_t)NEL);
    __half2* o3 = (__half2*)(g_wh + 2*(size_t)NEL);
    for (; i < NEL/2; i += stride) {
        float2 a = w1[i]; o1[i] = __floats2half2_rn(a.x, a.y);
        float2 b = w2[i]; o2[i] = __floats2half2_rn(b.x, b.y);
        float2 c = w3[i]; o3[i] = __floats2half2_rn(c.x, c.y);
    }
}

// ---- accumulate 3 rows over the 3 chunks with per-chunk barriers ----
template<bool PIN>
__device__ __forceinline__ void chunks_loop(
    const __half* w0, const __half* w1, const __half* w2,
    const float* __restrict__ sv, int ks, int lane,
    float& a0, float& a1, float& a2)
{
#pragma unroll
    for (int c = 0; c < NCHUNK; c++) {
        BAR_SYNC(1 + c, CNT_FWD);
        int kb = c*CHUNK + ks*256;
#pragma unroll
        for (int i = 0; i < 2; i++) {
            int k = kb + (i*32 + lane)*4;
            float4 v = *(const float4*)(sv + k);
#define ROW(AC, WP) do {                                                   \
            uint2 wa = PIN ? *(const uint2*)((WP) + k)                     \
                           : __ldg((const uint2*)((WP) + k));              \
            float2 fa = __half22float2(*(const __half2*)&wa.x);            \
            float2 fb = __half22float2(*(const __half2*)&wa.y);            \
            AC = fmaf(fa.x, v.x, AC); AC = fmaf(fa.y, v.y, AC);            \
            AC = fmaf(fb.x, v.z, AC); AC = fmaf(fb.y, v.w, AC); } while (0)
            ROW(a0, w0); ROW(a1, w1); ROW(a2, w2);
#undef ROW
        }
        BAR_ARRIVE(4 + c, CNT_FWD);
    }
}

__global__ void __launch_bounds__(NTHR, 1)
rnn_kernel(const float* __restrict__ x,  const float* __restrict__ state0,
           const float* __restrict__ B1, const float* __restrict__ B2,
           const float* __restrict__ B3, float* __restrict__ out) {
    extern __shared__ char smem[];
    __half* wpin = (__half*)smem;
    float*  sv   = (float*)(smem + SV_OFF);
    float*  spre = (float*)(smem + SPRE_OFF);

    const int tid  = threadIdx.x;
    const int lane = tid & 31;
    const int warp = tid >> 5;
    const int b    = blockIdx.x;

    const int rcount = 20 + (b < 112 ? 1 : 0);
    const int rstart = b*20 + (b < 112 ? b : 112);

    start_barrier();

    // ---- stage pinned weight rows (layer1 all + 12 rows of layer2) ----
    {
        const int npin = rcount + PIN_L2;
        int nvec = npin * (CDIM/8);
        for (int idx = tid; idx < nvec; idx += NTHR) {
            int p = idx / (CDIM/8);
            int c = idx % (CDIM/8);
            int l = (p < rcount) ? 0 : 1;
            int local = (p < rcount) ? p : p - rcount;
            const uint4* src = (const uint4*)(g_wh + (size_t)l*NEL + (size_t)(rstart+local)*CDIM);
            ((uint4*)(wpin + p*CDIM))[c] = src[c];
        }
    }
    __syncthreads();

    if (warp == 31) return;   // idle warp

    // T[k]: producers overlapping output rows [1024k, 1024k+1024)
    int Tk[NCHUNK];
#pragma unroll
    for (int k = 0; k < NCHUNK; k++) {
        int cnt = 0;
        for (int bb = 0; bb < NBLK; bb++) {
            int rs = 20*bb + (bb < 112 ? bb : 112);
            int rc = 20 + (bb < 112 ? 1 : 0);
            if (rs < (k+1)*CHUNK && rs + rc > k*CHUNK) cnt++;
        }
        Tk[k] = cnt;
    }

    if (warp >= NCOMPW) {
        // ================= STAGER WARP (one chunk each) =================
        const int c = warp - NCOMPW;            // 0..2
        const unsigned Tc = (unsigned)Tk[c];
        for (int t = 0; t < T_STEPS; t++) {
            for (int l = 0; l < 3; l++) {
                BAR_SYNC(4 + c, CNT_FWD);       // back-pressure (primed)
                const float* src;
                bool gated = true; unsigned tgt = 0; const unsigned* cp = 0;
                if (l == 0) {
                    if (c == 0) { src = x + (size_t)t*VOCAB; gated = false; }
                    else {
                        cp = &g_cnt[2][c]; tgt = (unsigned)t * Tc;
                        src = (t == 0) ? state0 + (c*CHUNK - VOCAB)
                                       : g_state[(t-1)&1] + (c*CHUNK - VOCAB);
                        gated = (t > 0);
                    }
                } else if (l == 1) {
                    cp = &g_cnt[0][c]; tgt = (unsigned)(t+1) * Tc;
                    src = g_h1[t&1] + c*CHUNK;
                } else {
                    cp = &g_cnt[1][c]; tgt = (unsigned)(t+1) * Tc;
                    src = g_h2[t&1] + c*CHUNK;
                }
                if (gated && lane == 0) {
                    unsigned v;
                    do {
                        asm volatile("ld.volatile.global.u32 %0,[%1];" : "=r"(v) : "l"(cp) : "memory");
                    } while (v < tgt);
                    __threadfence();
                }
                __syncwarp();
                const float4* s4 = (const float4*)src;
                float4* d4 = (float4*)(sv + c*CHUNK);
#pragma unroll
                for (int i = 0; i < CHUNK/128; i++)
                    d4[lane + 32*i] = __ldcg(&s4[lane + 32*i]);
                __threadfence_block();
                BAR_ARRIVE(1 + c, CNT_FWD);
            }
        }
    } else {
        // ================= COMPUTE WARP =================
        const int grp = warp >> 2;              // 0..6 (3 rows each)
        const int ks  = warp & 3;
        const int r0  = grp*3;
        const int l0 = min(r0,   rcount-1);
        const int l1 = min(r0+1, rcount-1);
        const int l2 = min(r0+2, rcount-1);
        const int klo = rstart >> 10;
        const int khi = (rstart + rcount - 1) >> 10;

        float myB1 = 0.f, myB2 = 0.f, myB3 = 0.f;
        if (tid < rcount) {
            myB1 = __ldg(&B1[rstart+tid]);
            myB2 = __ldg(&B2[rstart+tid]);
            myB3 = __ldg(&B3[rstart+tid]);
        }

        // prime back-pressure barriers (simulate phase -1 consumption)
#pragma unroll
        for (int c = 0; c < NCHUNK; c++) BAR_ARRIVE(4 + c, CNT_FWD);

        for (int t = 0; t < T_STEPS; t++) {
#pragma unroll
            for (int l = 0; l < 3; l++) {
                const __half* gw = g_wh + (size_t)l*NEL;
                int pin_g = (l == 0) ? 7 : (l == 1 ? 4 : 0);   // pinned groups
                const __half* wpinL = (l == 0) ? wpin : wpin + rcount*CDIM;

                float a0 = 0.f, a1 = 0.f, a2 = 0.f;
                if (grp < pin_g) {
                    chunks_loop<true >(wpinL + l0*CDIM, wpinL + l1*CDIM, wpinL + l2*CDIM,
                                       sv, ks, lane, a0, a1, a2);
                } else {
                    chunks_loop<false>(gw + (size_t)(rstart+l0)*CDIM,
                                       gw + (size_t)(rstart+l1)*CDIM,
                                       gw + (size_t)(rstart+l2)*CDIM,
                                       sv, ks, lane, a0, a1, a2);
                }
#pragma unroll
                for (int o = 16; o; o >>= 1) {
                    a0 += __shfl_xor_sync(0xffffffffu, a0, o);
                    a1 += __shfl_xor_sync(0xffffffffu, a1, o);
                    a2 += __shfl_xor_sync(0xffffffffu, a2, o);
                }
                if (lane == 0) {
                    if (r0   < rcount) spre[ks*32 + r0  ] = a0;
                    if (r0+1 < rcount) spre[ks*32 + r0+1] = a1;
                    if (r0+2 < rcount) spre[ks*32 + r0+2] = a2;
                }
                BAR_SYNC(7, CNT_CMP);           // spre writes -> visible

                // publish (warp 0 threads)
                if (tid < rcount) {
                    int j = rstart + tid;
                    float s = spre[tid] + spre[32+tid] + spre[64+tid] + spre[96+tid];
                    if (l == 0) {
                        __stcg(&g_h1[t&1][j], tanhf(s + myB1));
                    } else if (l == 1) {
                        __stcg(&g_h2[t&1][j], tanhf(s + myB2));
                    } else {
                        float o = s + myB3;
                        if (j < VOCAB) {
                            out[(size_t)t*VOCAB + j] = o;
                        } else {
                            __stcg(&g_state[t&1][j - VOCAB], o);
                            if (t == T_STEPS-1)
                                out[(size_t)T_STEPS*VOCAB + (j - VOCAB)] = o;
                        }
                    }
                }
                if (warp == 0) {
                    __syncwarp();
                    if (lane == 0) {
                        __threadfence();
                        atomicAdd(&g_cnt[l][klo], 1u);
                        if (khi != klo) atomicAdd(&g_cnt[l][khi], 1u);
                    }
                }
                BAR_SYNC(8, CNT_CMP);           // WAR fix: spre reads done before next phase writes
            }
        }
    }
}

extern "C" void kernel_launch(void* const* d_in, const int* in_sizes, int n_in,
                              void* d_out, int out_size) {
    const float* x  = (const float*)d_in[0];
    const float* st = (const float*)d_in[1];
    const float* W1 = (const float*)d_in[2];
    const float* B1 = (const float*)d_in[3];
    const float* W2 = (const float*)d_in[4];
    const float* B2 = (const float*)d_in[5];
    const float* W3 = (const float*)d_in[6];
    const float* B3 = (const float*)d_in[7];
    (void)in_sizes; (void)n_in; (void)out_size;

    cudaFuncSetAttribute(rnn_kernel, cudaFuncAttributeMaxDynamicSharedMemorySize, SMEM_TOTAL);

    conv_kernel<<<2048, 256>>>(W1, W2, W3);
    rnn_kernel<<<NBLK, NTHR, SMEM_TOTAL>>>(x, st, B1, B2, B3, (float*)d_out);
}